// round 7
// baseline (speedup 1.0000x reference)
#include <cuda_runtime.h>
#include <math.h>

#define BB   16
#define CINC 12
#define TLEN 16352
#define NAC  128
#define LLAT 512
#define CH1  64
#define NRECON (BB*CINC*TLEN)

typedef unsigned long long ull;

__device__ __forceinline__ void fma2(ull& d, ull a, ull b) {
    asm("fma.rn.f32x2 %0, %1, %2, %0;" : "+l"(d) : "l"(a), "l"(b));
}
__device__ __forceinline__ ull pack2(float x, float y) {
    ull r; asm("mov.b64 %0, {%1,%2};" : "=l"(r) : "f"(x), "f"(y)); return r;
}
__device__ __forceinline__ void unpack2(float& x, float& y, ull v) {
    asm("mov.b64 {%0,%1}, %2;" : "=f"(x), "=f"(y) : "l"(v));
}

// ---------------- device scratch ----------------
__device__ float g_mean[BB*CINC];
__device__ float g_std [BB*CINC];
__device__ float g_h [BB*CH1*LLAT];
__device__ float g_z [BB*NAC*LLAT];
__device__ float g_R [BB*NAC*LLAT];
__device__ float g_zc[BB*NAC*LLAT];
__device__ float g_shp[NAC*NAC*64];
__device__ float g_W4 [NAC*NAC*4*17];
__device__ float g_W2 [NAC*NAC*2*33];
__device__ float g_Wd [CINC*NAC*32*3];
__device__ float g_l1;

// ---------------- per-(b,c) mean/std (+ g_l1 zero) ----------------
__global__ void k_stats(const float* __restrict__ x) {
    int row = blockIdx.x, tid = threadIdx.x;
    if (row == 0 && tid == 0) g_l1 = 0.f;
    const float* xr = x + (size_t)row * TLEN;
    float s = 0.f, s2 = 0.f;
    for (int i = tid; i < TLEN; i += 256) { float v = xr[i]; s += v; s2 += v * v; }
    __shared__ float sh[256], sh2[256];
    sh[tid] = s; sh2[tid] = s2; __syncthreads();
    for (int o = 128; o > 0; o >>= 1) {
        if (tid < o) { sh[tid] += sh[tid+o]; sh2[tid] += sh2[tid+o]; }
        __syncthreads();
    }
    if (tid == 0) {
        float m = sh[0] / (float)TLEN;
        float var = sh2[0] / (float)TLEN - m * m;
        g_mean[row] = m; g_std[row] = sqrtf(var + 1e-5f);
    }
}

// ---------------- stem conv: K=64, stride 32, pad(32,32), fused norm+relu ----------------
__global__ void __launch_bounds__(256) k_stem(const float* __restrict__ x,
                                              const float* __restrict__ w1,
                                              const float* __restrict__ b1) {
    int b = blockIdx.y, t0 = blockIdx.x * 16, tid = threadIdx.x;
    __shared__ float xs[CINC * 544];
    __shared__ float mloc[CINC], isloc[CINC];
    if (tid < CINC) { mloc[tid] = g_mean[b*CINC+tid]; isloc[tid] = 1.f / g_std[b*CINC+tid]; }
    __syncthreads();
    for (int idx = tid; idx < CINC * 544; idx += 256) {
        int i = idx / 544, xl = idx % 544;
        int p = 32 * t0 - 32 + xl;
        float v = 0.f;
        if (p >= 0 && p < TLEN) v = (x[(size_t)(b*CINC+i)*TLEN + p] - mloc[i]) * isloc[i];
        xs[idx] = v;
    }
    __syncthreads();
    int c = tid & 63, tg = tid >> 6;
    float bc = b1[c];
    float acc[4] = {bc, bc, bc, bc};
    const float4* w4p = (const float4*)(w1 + c * CINC * 64);
    for (int i = 0; i < CINC; i++) {
        const float* xbase = xs + i * 544 + tg * 128;
        #pragma unroll
        for (int k4 = 0; k4 < 16; k4++) {
            float4 w = w4p[i * 16 + k4];
            #pragma unroll
            for (int tl = 0; tl < 4; tl++) {
                const float* xr2 = xbase + tl * 32 + k4 * 4;
                acc[tl] += w.x*xr2[0] + w.y*xr2[1] + w.z*xr2[2] + w.w*xr2[3];
            }
        }
    }
    #pragma unroll
    for (int tl = 0; tl < 4; tl++)
        g_h[(b*CH1 + c)*LLAT + t0 + tg*4 + tl] = fmaxf(acc[tl], 0.f);
}

// ---------------- 1x1 conv ----------------
__global__ void __launch_bounds__(256) k_point(const float* __restrict__ w2,
                                               const float* __restrict__ b2,
                                               const float* __restrict__ sscale) {
    int b = blockIdx.y, t0 = blockIdx.x * 32, tid = threadIdx.x;
    __shared__ float hs[CH1 * 32];
    __shared__ float w2s[NAC * 65];
    for (int idx = tid; idx < CH1 * 32; idx += 256) {
        int cch = idx >> 5, tl = idx & 31;
        hs[cch*32 + tl] = g_h[(b*CH1 + cch)*LLAT + t0 + tl];
    }
    for (int idx = tid; idx < NAC * CH1; idx += 256) {
        int o = idx >> 6, cch = idx & 63;
        w2s[o*65 + cch] = w2[o*CH1 + cch];
    }
    __syncthreads();
    int o = tid & 127, th = tid >> 7;
    float sc = sscale[0], bo = b2[o];
    for (int tl = th*16; tl < th*16 + 16; tl++) {
        float acc = bo;
        #pragma unroll 8
        for (int cch = 0; cch < CH1; cch++) acc += hs[cch*32 + tl] * w2s[o*65 + cch];
        g_z[(b*NAC + o)*LLAT + t0 + tl] = acc * sc;
    }
}

// ---------------- shapelet normalization ----------------
__global__ void k_shpnorm(const float* __restrict__ shp) {
    int row = blockIdx.x * 256 + threadIdx.x;
    if (row >= NAC*NAC) return;
    const float4* s4 = (const float4*)(shp + row*64);
    float s = 0.f;
    #pragma unroll
    for (int i = 0; i < 16; i++) { float4 v = s4[i]; s += v.x*v.x+v.y*v.y+v.z*v.z+v.w*v.w; }
    float inv = 1.f / fmaxf(sqrtf(s), 1e-8f);
    float4* d4 = (float4*)(g_shp + row*64);
    #pragma unroll
    for (int i = 0; i < 16; i++) {
        float4 v = s4[i]; v.x*=inv; v.y*=inv; v.z*=inv; v.w*=inv; d4[i] = v;
    }
}

// ---------------- phase weights ----------------
template <int S>
__global__ void k_buildW(const float* __restrict__ ext) {
    constexpr int OC = (S == 32) ? CINC : NAC;
    constexpr int D  = (S == 32) ? 3 : (S == 4) ? 17 : 33;
    constexpr int D0 = (S == 32) ? -1 : (S == 4) ? -8 : -16;
    constexpr int total = OC * NAC * S * D;
    float* dst = (S == 32) ? g_Wd : (S == 4) ? g_W4 : g_W2;
    const float* src = (S == 32) ? ext : g_shp;
    int idx = blockIdx.x * 256 + threadIdx.x;
    if (idx >= total) return;
    int di = idx % D;
    int r  = (idx / D) % S;
    int a  = (idx / (D * S)) % NAC;
    int o  =  idx / (D * S * NAC);
    int k0 = S * (D0 + di) + 31 - r;
    float s = 0.f;
    #pragma unroll
    for (int m = 0; m < S; m++) {
        int k = k0 + m;
        if (k >= 0 && k < 64) s += src[(o*NAC + a)*64 + k];
    }
    dst[idx] = s;
}

// ---------------- pooling / residual + L1 ----------------
__global__ void k_pool4() {
    int row = blockIdx.x, j = threadIdx.x;
    const float* zr = g_z + (size_t)row * LLAT;
    float v = 0.25f * (zr[4*j] + zr[4*j+1] + zr[4*j+2] + zr[4*j+3]);
    g_zc[row*128 + j] = v;
    __shared__ float red[128];
    red[j] = fabsf(v); __syncthreads();
    for (int o = 64; o > 0; o >>= 1) { if (j < o) red[j] += red[j+o]; __syncthreads(); }
    if (j == 0) atomicAdd(&g_l1, red[0] * (1.f / (16.f*128.f*128.f)));
}
__global__ void k_rp2() {
    int row = blockIdx.x, j = threadIdx.x;
    const float* zr = g_z + (size_t)row * LLAT;
    const float* rr = g_R + (size_t)row * LLAT;
    float v = 0.5f * ((zr[2*j]-rr[2*j]) + (zr[2*j+1]-rr[2*j+1]));
    g_zc[row*256 + j] = v;
    __shared__ float red[256];
    red[j] = fabsf(v); __syncthreads();
    for (int o = 128; o > 0; o >>= 1) { if (j < o) red[j] += red[j+o]; __syncthreads(); }
    if (j == 0) atomicAdd(&g_l1, red[0] * (1.f / (16.f*128.f*256.f)));
}
__global__ void k_r1() {
    int row = blockIdx.x, j = threadIdx.x;
    const float* zr = g_z + (size_t)row * LLAT;
    const float* rr = g_R + (size_t)row * LLAT;
    float v = zr[j] - rr[j];
    g_zc[row*512 + j] = v;
    __shared__ float red[512];
    red[j] = fabsf(v); __syncthreads();
    for (int o = 256; o > 0; o >>= 1) { if (j < o) red[j] += red[j+o]; __syncthreads(); }
    if (j == 0) atomicAdd(&g_l1, red[0] * (1.f / (16.f*128.f*512.f)));
}

// ---------------- coarse conv workhorse (f32x2, duplicated-z smem, 2 blocks/SM) ----------------
// out[b,o,S*q+r] (=|+=) sum_a sum_d W[o,a,r,d] * zc[b,a, q+D0+d]
template <int S, int D, int AC, bool ACCUM>
__global__ void __launch_bounds__(256, 2) k_conv() {
    constexpr int QT  = 64;
    constexpr int Lc  = LLAT / S;
    constexpr int WIN = QT + D - 1;
    constexpr int Dp  = ((D & 1) == 0) ? D + 1 : D;
    constexpr int D0  = (S == 1) ? -31 : (S == 2) ? -16 : -8;
    const float* __restrict__ W = (S == 4) ? g_W4 : (S == 2) ? g_W2 : g_shp;

    extern __shared__ float sm[];
    float* zcs = sm;                     // AC * WIN * 2 (duplicated pairs)
    float* Ws  = sm + AC * WIN * 2;      // AC * 32 * Dp * 2 (pair-interleaved)

    int qb = blockIdx.x * QT;
    int o0 = blockIdx.y * 64;
    int b  = blockIdx.z / S;
    int r  = blockIdx.z % S;
    int tid = threadIdx.x;

    int oi = tid & 31, qi = tid >> 5;
    ull accp[8];
    #pragma unroll
    for (int t = 0; t < 8; t++) accp[t] = 0ULL;

    for (int a0 = 0; a0 < NAC; a0 += AC) {
        __syncthreads();
        for (int idx = tid; idx < AC * WIN; idx += 256) {
            int aoff = idx / WIN, xx = idx % WIN;
            int ci = qb + D0 + xx;
            float v = (ci >= 0 && ci < Lc) ? g_zc[(b*NAC + a0 + aoff)*Lc + ci] : 0.f;
            *(ull*)(zcs + idx*2) = pack2(v, v);
        }
        for (int idx = tid; idx < AC * 64 * D; idx += 256) {
            int aoff = idx / (64 * D);
            int rem  = idx % (64 * D);
            int ol = rem / D, di = rem % D;
            int oi2 = ol >> 1, u = ol & 1;
            Ws[((aoff*32 + oi2)*Dp + di)*2 + u] =
                W[(((o0 + ol)*NAC + (a0 + aoff))*S + r)*D + di];
        }
        __syncthreads();
        for (int aoff = 0; aoff < AC; aoff++) {
            const float* zrow = zcs + (aoff*WIN + qi*8)*2;
            const float* wrow = Ws + aoff*32*Dp*2;
            #pragma unroll
            for (int dc = 0; dc < D; dc += 8) {
                ull zz[15];
                #pragma unroll
                for (int xx = 0; xx < 15; xx++)
                    if (dc + xx < D + 7) zz[xx] = *(const ull*)(zrow + (dc + xx)*2);
                #pragma unroll
                for (int j = 0; j < 8; j++)
                    if (dc + j < D) {
                        ull wp = *(const ull*)(wrow + (oi*Dp + dc + j)*2);
                        #pragma unroll
                        for (int t = 0; t < 8; t++)
                            fma2(accp[t], wp, zz[t + j]);
                    }
            }
        }
    }

    #pragma unroll
    for (int t = 0; t < 8; t++) {
        float v0, v1;
        unpack2(v0, v1, accp[t]);
        int q = qb + qi*8 + t;
        int o = o0 + oi*2;
        int i0 = (b*NAC + o    )*LLAT + S*q + r;
        int i1 = (b*NAC + o + 1)*LLAT + S*q + r;
        if (ACCUM) { g_R[i0] += v0; g_R[i1] += v1; }
        else       { g_R[i0]  = v0; g_R[i1]  = v1; }
    }
}

// ---------------- decoder: 3-tap coarse conv (x32 upsample) + denorm, a-chunked ----------------
__global__ void __launch_bounds__(256) k_dec(const float* __restrict__ dec_b,
                                             float* __restrict__ out) {
    extern __shared__ float sm[];
    float* zcs = sm;              // 32*66*2 (duplicated)
    float* Ws  = sm + 32*66*2;    // 32*32*3*2
    int q0 = blockIdx.x * 64;
    int c0 = blockIdx.y * 2;
    int b  = blockIdx.z;
    int tid = threadIdx.x;
    int ri = tid & 31, qi = tid >> 5;

    ull accp[8];
    #pragma unroll
    for (int t = 0; t < 8; t++) accp[t] = 0ULL;

    for (int a0 = 0; a0 < NAC; a0 += 32) {
        __syncthreads();
        for (int idx = tid; idx < 32*66; idx += 256) {
            int aoff = idx / 66, lq = idx % 66;
            int q = q0 - 1 + lq;
            float v = (q >= 0 && q < LLAT) ? g_R[(b*NAC + a0 + aoff)*LLAT + q] : 0.f;
            *(ull*)(zcs + idx*2) = pack2(v, v);
        }
        for (int idx = tid; idx < 32*32*3*2; idx += 256) {
            int u = idx & 1;
            int v = idx >> 1;
            int j = v % 3;
            int rr = (v / 3) & 31;
            int aoff = v / 96;
            Ws[idx] = g_Wd[(((c0 + u)*NAC + a0 + aoff)*32 + rr)*3 + j];
        }
        __syncthreads();
        for (int aoff = 0; aoff < 32; aoff++) {
            const float* zrow = zcs + (aoff*66 + qi*8)*2;
            ull zz[10];
            #pragma unroll
            for (int xx = 0; xx < 10; xx++) zz[xx] = *(const ull*)(zrow + xx*2);
            const float* wp = Ws + aoff*32*3*2;
            #pragma unroll
            for (int j = 0; j < 3; j++) {
                ull w = *(const ull*)(wp + (ri*3 + j)*2);
                #pragma unroll
                for (int t = 0; t < 8; t++)
                    fma2(accp[t], w, zz[t + j]);
            }
        }
    }

    float m0 = g_mean[b*CINC + c0],     s0 = g_std[b*CINC + c0],     db0 = dec_b[c0];
    float m1 = g_mean[b*CINC + c0 + 1], s1 = g_std[b*CINC + c0 + 1], db1 = dec_b[c0 + 1];
    #pragma unroll
    for (int t = 0; t < 8; t++) {
        float v0, v1;
        unpack2(v0, v1, accp[t]);
        int q = q0 + qi*8 + t;
        int tt = 32*q + ri;
        if (tt < TLEN) {
            out[((size_t)(b*CINC + c0    ))*TLEN + tt] = (v0 + db0) * s0 + m0;
            out[((size_t)(b*CINC + c0 + 1))*TLEN + tt] = (v1 + db1) * s1 + m1;
        }
    }
}

__global__ void k_final(float* out) {
    if (threadIdx.x == 0) { out[NRECON] = 0.f; out[NRECON+1] = g_l1 * 0.01f; }
}

// ---------------- launch ----------------
extern "C" void kernel_launch(void* const* d_in, const int* in_sizes, int n_in,
                              void* d_out, int out_size) {
    const float* x   = (const float*)d_in[0];
    const float* w1  = (const float*)d_in[1];
    const float* b1  = (const float*)d_in[2];
    const float* w2  = (const float*)d_in[3];
    const float* b2  = (const float*)d_in[4];
    const float* ssc = (const float*)d_in[5];
    const float* shp = (const float*)d_in[6];
    const float* dw  = (const float*)d_in[7];
    const float* db  = (const float*)d_in[8];
    float* out = (float*)d_out;

    const int SMEM4 = (16*80*2 + 16*32*17*2) * 4;  // 79872
    const int SMEM2 = (8*96*2  + 8*32*33*2) * 4;   // 73728
    const int SMEM1 = (4*127*2 + 4*32*65*2) * 4;   // 70624
    const int SMEMD = (32*66*2 + 32*32*3*2) * 4;   // 41472
    cudaFuncSetAttribute(k_conv<4,17,16,false>, cudaFuncAttributeMaxDynamicSharedMemorySize, SMEM4);
    cudaFuncSetAttribute(k_conv<2,33, 8,true >, cudaFuncAttributeMaxDynamicSharedMemorySize, SMEM2);
    cudaFuncSetAttribute(k_conv<1,64, 4,true >, cudaFuncAttributeMaxDynamicSharedMemorySize, SMEM1);
    cudaFuncSetAttribute(k_dec,                 cudaFuncAttributeMaxDynamicSharedMemorySize, SMEMD);

    k_stats<<<BB*CINC, 256>>>(x);
    k_shpnorm<<<(NAC*NAC + 255)/256, 256>>>(shp);
    k_buildW<4> <<<(NAC*NAC*4*17 + 255)/256, 256>>>(dw);
    k_buildW<2> <<<(NAC*NAC*2*33 + 255)/256, 256>>>(dw);
    k_buildW<32><<<(CINC*NAC*32*3 + 255)/256, 256>>>(dw);
    k_stem<<<dim3(LLAT/16, BB), 256>>>(x, w1, b1);
    k_point<<<dim3(LLAT/32, BB), 256>>>(w2, b2, ssc);
    k_pool4<<<BB*NAC, 128>>>();
    k_conv<4,17,16,false><<<dim3(2, 2, BB*4), 256, SMEM4>>>();
    k_rp2<<<BB*NAC, 256>>>();
    k_conv<2,33, 8,true ><<<dim3(4, 2, BB*2), 256, SMEM2>>>();
    k_r1<<<BB*NAC, 512>>>();
    k_conv<1,64, 4,true ><<<dim3(8, 2, BB  ), 256, SMEM1>>>();
    k_dec<<<dim3(8, 6, BB), 256, SMEMD>>>(db, out);
    k_final<<<1, 32>>>(out);
}

// round 8
// speedup vs baseline: 1.1524x; 1.1524x over previous
#include <cuda_runtime.h>
#include <math.h>

#define BB   16
#define CINC 12
#define TLEN 16352
#define NAC  128
#define LLAT 512
#define CH1  64
#define NRECON (BB*CINC*TLEN)

typedef unsigned long long ull;

__device__ __forceinline__ void fma2(ull& d, ull a, ull b) {
    asm("fma.rn.f32x2 %0, %1, %2, %0;" : "+l"(d) : "l"(a), "l"(b));
}
__device__ __forceinline__ ull pack2(float x, float y) {
    ull r; asm("mov.b64 %0, {%1,%2};" : "=l"(r) : "f"(x), "f"(y)); return r;
}
__device__ __forceinline__ void unpack2(float& x, float& y, ull v) {
    asm("mov.b64 {%0,%1}, %2;" : "=f"(x), "=f"(y) : "l"(v));
}
__device__ __forceinline__ void cpa4(unsigned dst, const float* src) {
    asm volatile("cp.async.ca.shared.global [%0], [%1], 4;" :: "r"(dst), "l"(src));
}

// ---------------- device scratch ----------------
__device__ float g_mean[BB*CINC];
__device__ float g_std [BB*CINC];
__device__ float g_h [BB*CH1*LLAT];
__device__ float g_z [BB*NAC*LLAT];
__device__ float g_R [BB*NAC*LLAT];
__device__ float g_zc[BB*NAC*LLAT];
__device__ float g_shp[NAC*NAC*64];
__device__ float g_W4 [NAC*NAC*4*17];
__device__ float g_W2 [NAC*NAC*2*33];
__device__ float g_Wd [CINC*NAC*32*3];
__device__ float g_l1;

// ---------------- per-(b,c) mean/std (+ g_l1 zero) ----------------
__global__ void k_stats(const float* __restrict__ x) {
    int row = blockIdx.x, tid = threadIdx.x;
    if (row == 0 && tid == 0) g_l1 = 0.f;
    const float* xr = x + (size_t)row * TLEN;
    float s = 0.f, s2 = 0.f;
    for (int i = tid; i < TLEN; i += 256) { float v = xr[i]; s += v; s2 += v * v; }
    __shared__ float sh[256], sh2[256];
    sh[tid] = s; sh2[tid] = s2; __syncthreads();
    for (int o = 128; o > 0; o >>= 1) {
        if (tid < o) { sh[tid] += sh[tid+o]; sh2[tid] += sh2[tid+o]; }
        __syncthreads();
    }
    if (tid == 0) {
        float m = sh[0] / (float)TLEN;
        float var = sh2[0] / (float)TLEN - m * m;
        g_mean[row] = m; g_std[row] = sqrtf(var + 1e-5f);
    }
}

// ---------------- stem conv: K=64, stride 32, pad(32,32), fused norm+relu ----------------
__global__ void __launch_bounds__(256) k_stem(const float* __restrict__ x,
                                              const float* __restrict__ w1,
                                              const float* __restrict__ b1) {
    int b = blockIdx.y, t0 = blockIdx.x * 16, tid = threadIdx.x;
    __shared__ float xs[CINC * 544];
    __shared__ float mloc[CINC], isloc[CINC];
    if (tid < CINC) { mloc[tid] = g_mean[b*CINC+tid]; isloc[tid] = 1.f / g_std[b*CINC+tid]; }
    __syncthreads();
    for (int idx = tid; idx < CINC * 544; idx += 256) {
        int i = idx / 544, xl = idx % 544;
        int p = 32 * t0 - 32 + xl;
        float v = 0.f;
        if (p >= 0 && p < TLEN) v = (x[(size_t)(b*CINC+i)*TLEN + p] - mloc[i]) * isloc[i];
        xs[idx] = v;
    }
    __syncthreads();
    int c = tid & 63, tg = tid >> 6;
    float bc = b1[c];
    float acc[4] = {bc, bc, bc, bc};
    const float4* w4p = (const float4*)(w1 + c * CINC * 64);
    for (int i = 0; i < CINC; i++) {
        const float* xbase = xs + i * 544 + tg * 128;
        #pragma unroll
        for (int k4 = 0; k4 < 16; k4++) {
            float4 w = w4p[i * 16 + k4];
            #pragma unroll
            for (int tl = 0; tl < 4; tl++) {
                const float* xr2 = xbase + tl * 32 + k4 * 4;
                acc[tl] += w.x*xr2[0] + w.y*xr2[1] + w.z*xr2[2] + w.w*xr2[3];
            }
        }
    }
    #pragma unroll
    for (int tl = 0; tl < 4; tl++)
        g_h[(b*CH1 + c)*LLAT + t0 + tg*4 + tl] = fmaxf(acc[tl], 0.f);
}

// ---------------- 1x1 conv ----------------
__global__ void __launch_bounds__(256) k_point(const float* __restrict__ w2,
                                               const float* __restrict__ b2,
                                               const float* __restrict__ sscale) {
    int b = blockIdx.y, t0 = blockIdx.x * 32, tid = threadIdx.x;
    __shared__ float hs[CH1 * 32];
    __shared__ float w2s[NAC * 65];
    for (int idx = tid; idx < CH1 * 32; idx += 256) {
        int cch = idx >> 5, tl = idx & 31;
        hs[cch*32 + tl] = g_h[(b*CH1 + cch)*LLAT + t0 + tl];
    }
    for (int idx = tid; idx < NAC * CH1; idx += 256) {
        int o = idx >> 6, cch = idx & 63;
        w2s[o*65 + cch] = w2[o*CH1 + cch];
    }
    __syncthreads();
    int o = tid & 127, th = tid >> 7;
    float sc = sscale[0], bo = b2[o];
    for (int tl = th*16; tl < th*16 + 16; tl++) {
        float acc = bo;
        #pragma unroll 8
        for (int cch = 0; cch < CH1; cch++) acc += hs[cch*32 + tl] * w2s[o*65 + cch];
        g_z[(b*NAC + o)*LLAT + t0 + tl] = acc * sc;
    }
}

// ---------------- shapelet normalization ----------------
__global__ void k_shpnorm(const float* __restrict__ shp) {
    int row = blockIdx.x * 256 + threadIdx.x;
    if (row >= NAC*NAC) return;
    const float4* s4 = (const float4*)(shp + row*64);
    float s = 0.f;
    #pragma unroll
    for (int i = 0; i < 16; i++) { float4 v = s4[i]; s += v.x*v.x+v.y*v.y+v.z*v.z+v.w*v.w; }
    float inv = 1.f / fmaxf(sqrtf(s), 1e-8f);
    float4* d4 = (float4*)(g_shp + row*64);
    #pragma unroll
    for (int i = 0; i < 16; i++) {
        float4 v = s4[i]; v.x*=inv; v.y*=inv; v.z*=inv; v.w*=inv; d4[i] = v;
    }
}

// ---------------- phase weights ----------------
template <int S>
__global__ void k_buildW(const float* __restrict__ ext) {
    constexpr int OC = (S == 32) ? CINC : NAC;
    constexpr int D  = (S == 32) ? 3 : (S == 4) ? 17 : 33;
    constexpr int D0 = (S == 32) ? -1 : (S == 4) ? -8 : -16;
    constexpr int total = OC * NAC * S * D;
    float* dst = (S == 32) ? g_Wd : (S == 4) ? g_W4 : g_W2;
    const float* src = (S == 32) ? ext : g_shp;
    int idx = blockIdx.x * 256 + threadIdx.x;
    if (idx >= total) return;
    int di = idx % D;
    int r  = (idx / D) % S;
    int a  = (idx / (D * S)) % NAC;
    int o  =  idx / (D * S * NAC);
    int k0 = S * (D0 + di) + 31 - r;
    float s = 0.f;
    #pragma unroll
    for (int m = 0; m < S; m++) {
        int k = k0 + m;
        if (k >= 0 && k < 64) s += src[(o*NAC + a)*64 + k];
    }
    dst[idx] = s;
}

// ---------------- pooling / residual + L1 ----------------
__global__ void k_pool4() {
    int row = blockIdx.x, j = threadIdx.x;
    const float* zr = g_z + (size_t)row * LLAT;
    float v = 0.25f * (zr[4*j] + zr[4*j+1] + zr[4*j+2] + zr[4*j+3]);
    g_zc[row*128 + j] = v;
    __shared__ float red[128];
    red[j] = fabsf(v); __syncthreads();
    for (int o = 64; o > 0; o >>= 1) { if (j < o) red[j] += red[j+o]; __syncthreads(); }
    if (j == 0) atomicAdd(&g_l1, red[0] * (1.f / (16.f*128.f*128.f)));
}
__global__ void k_rp2() {
    int row = blockIdx.x, j = threadIdx.x;
    const float* zr = g_z + (size_t)row * LLAT;
    const float* rr = g_R + (size_t)row * LLAT;
    float v = 0.5f * ((zr[2*j]-rr[2*j]) + (zr[2*j+1]-rr[2*j+1]));
    g_zc[row*256 + j] = v;
    __shared__ float red[256];
    red[j] = fabsf(v); __syncthreads();
    for (int o = 128; o > 0; o >>= 1) { if (j < o) red[j] += red[j+o]; __syncthreads(); }
    if (j == 0) atomicAdd(&g_l1, red[0] * (1.f / (16.f*128.f*256.f)));
}
__global__ void k_r1() {
    int row = blockIdx.x, j = threadIdx.x;
    const float* zr = g_z + (size_t)row * LLAT;
    const float* rr = g_R + (size_t)row * LLAT;
    float v = zr[j] - rr[j];
    g_zc[row*512 + j] = v;
    __shared__ float red[512];
    red[j] = fabsf(v); __syncthreads();
    for (int o = 256; o > 0; o >>= 1) { if (j < o) red[j] += red[j+o]; __syncthreads(); }
    if (j == 0) atomicAdd(&g_l1, red[0] * (1.f / (16.f*128.f*512.f)));
}

// ---------------- coarse conv workhorse (f32x2, cp.async double-buffered, 2 blocks/SM) ----------------
// out[b,o,S*q+r] (=|+=) sum_a sum_d W[o,a,r,d] * zc[b,a, q+D0+d]
template <int S, int D, int AC, bool ACCUM>
__global__ void __launch_bounds__(256, 2) k_conv() {
    constexpr int QT  = 64;
    constexpr int Lc  = LLAT / S;
    constexpr int WIN = QT + D - 1;
    constexpr int Dp  = ((D & 1) == 0) ? D + 1 : D;
    constexpr int D0  = (S == 1) ? -31 : (S == 2) ? -16 : -8;
    constexpr int ZN  = AC * WIN;
    constexpr int WN  = AC * 32 * Dp * 2;
    constexpr int BUF = ZN + WN;
    constexpr int NCH = NAC / AC;
    const float* __restrict__ W = (S == 4) ? g_W4 : (S == 2) ? g_W2 : g_shp;

    extern __shared__ float sm[];

    int qb = blockIdx.x * QT;
    int o0 = blockIdx.y * 64;
    int b  = blockIdx.z / S;
    int r  = blockIdx.z % S;
    int tid = threadIdx.x;

    int oi = tid & 31, qi = tid >> 5;
    ull accp[8];
    #pragma unroll
    for (int t = 0; t < 8; t++) accp[t] = 0ULL;

    // stage chunk `a0` into buffer `bsel` (async)
    auto stage = [&](int bsel, int a0) {
        float* zcs = sm + bsel * BUF;
        float* Ws  = zcs + ZN;
        unsigned za = (unsigned)__cvta_generic_to_shared(zcs);
        unsigned wa = (unsigned)__cvta_generic_to_shared(Ws);
        for (int idx = tid; idx < ZN; idx += 256) {
            int aoff = idx / WIN, xx = idx % WIN;
            int ci = qb + D0 + xx;
            if (ci >= 0 && ci < Lc) cpa4(za + idx*4, &g_zc[(b*NAC + a0 + aoff)*Lc + ci]);
            else zcs[idx] = 0.f;
        }
        for (int idx = tid; idx < AC * 64 * D; idx += 256) {
            int aoff = idx / (64 * D);
            int rem  = idx % (64 * D);
            int ol = rem / D, di = rem % D;
            int dst = ((aoff*32 + (ol >> 1))*Dp + di)*2 + (ol & 1);
            cpa4(wa + dst*4, &W[(((o0 + ol)*NAC + (a0 + aoff))*S + r)*D + di]);
        }
        asm volatile("cp.async.commit_group;" ::: "memory");
    };

    stage(0, 0);

    for (int c = 0; c < NCH; c++) {
        __syncthreads();                       // prior compute done -> safe to overwrite alt buffer
        if (c + 1 < NCH) {
            stage((c + 1) & 1, (c + 1) * AC);
            asm volatile("cp.async.wait_group 1;" ::: "memory");  // chunk c complete
        } else {
            asm volatile("cp.async.wait_group 0;" ::: "memory");
        }
        __syncthreads();                       // chunk c visible to all threads

        const float* zcb = sm + (c & 1) * BUF;
        const float* Wsb = zcb + ZN;
        for (int aoff = 0; aoff < AC; aoff++) {
            const float* zrow = zcb + aoff*WIN + qi*8;
            const float* wrow = Wsb + aoff*32*Dp*2;
            #pragma unroll
            for (int dc = 0; dc < D; dc += 8) {
                ull zz[15];
                #pragma unroll
                for (int xx = 0; xx < 15; xx++)
                    if (dc + xx < D + 7) { float v = zrow[dc + xx]; zz[xx] = pack2(v, v); }
                #pragma unroll
                for (int j = 0; j < 8; j++)
                    if (dc + j < D) {
                        ull wp = *(const ull*)(wrow + (oi*Dp + dc + j)*2);
                        #pragma unroll
                        for (int t = 0; t < 8; t++)
                            fma2(accp[t], wp, zz[t + j]);
                    }
            }
        }
    }

    #pragma unroll
    for (int t = 0; t < 8; t++) {
        float v0, v1;
        unpack2(v0, v1, accp[t]);
        int q = qb + qi*8 + t;
        int o = o0 + oi*2;
        int i0 = (b*NAC + o    )*LLAT + S*q + r;
        int i1 = (b*NAC + o + 1)*LLAT + S*q + r;
        if (ACCUM) { g_R[i0] += v0; g_R[i1] += v1; }
        else       { g_R[i0]  = v0; g_R[i1]  = v1; }
    }
}

// ---------------- decoder: 3-tap coarse conv (x32 upsample) + denorm, packed over c-pair ----------------
__global__ void __launch_bounds__(256) k_dec(const float* __restrict__ dec_b,
                                             float* __restrict__ out) {
    extern __shared__ float sm[];
    float* zcs = sm;             // 128*66
    float* Ws  = sm + 128*66;    // 32*32*3*2 = 6144 (pair-interleaved over c)
    int q0 = blockIdx.x * 64;
    int c0 = blockIdx.y * 2;
    int b  = blockIdx.z;
    int tid = threadIdx.x;
    int ri = tid & 31, qi = tid >> 5;

    for (int idx = tid; idx < 128*66; idx += 256) {
        int a = idx / 66, lq = idx % 66;
        int q = q0 - 1 + lq;
        zcs[idx] = (q >= 0 && q < LLAT) ? g_R[(b*NAC + a)*LLAT + q] : 0.f;
    }

    ull accp[8];
    #pragma unroll
    for (int t = 0; t < 8; t++) accp[t] = 0ULL;

    for (int a0 = 0; a0 < NAC; a0 += 32) {
        __syncthreads();
        for (int idx = tid; idx < 32*32*3*2; idx += 256) {
            int u = idx & 1;
            int v = idx >> 1;
            int j = v % 3;
            int rr = (v / 3) & 31;
            int aoff = v / 96;
            Ws[idx] = g_Wd[(((c0 + u)*NAC + a0 + aoff)*32 + rr)*3 + j];
        }
        __syncthreads();
        for (int aoff = 0; aoff < 32; aoff++) {
            const float* zrow = zcs + (a0+aoff)*66 + qi*8;
            ull zz[10];
            #pragma unroll
            for (int xx = 0; xx < 10; xx++) { float v = zrow[xx]; zz[xx] = pack2(v, v); }
            const float* wp = Ws + aoff*32*3*2;
            #pragma unroll
            for (int j = 0; j < 3; j++) {
                ull w = *(const ull*)(wp + (ri*3 + j)*2);
                #pragma unroll
                for (int t = 0; t < 8; t++)
                    fma2(accp[t], w, zz[t + j]);
            }
        }
    }

    float m0 = g_mean[b*CINC + c0],     s0 = g_std[b*CINC + c0],     db0 = dec_b[c0];
    float m1 = g_mean[b*CINC + c0 + 1], s1 = g_std[b*CINC + c0 + 1], db1 = dec_b[c0 + 1];
    #pragma unroll
    for (int t = 0; t < 8; t++) {
        float v0, v1;
        unpack2(v0, v1, accp[t]);
        int q = q0 + qi*8 + t;
        int tt = 32*q + ri;
        if (tt < TLEN) {
            out[((size_t)(b*CINC + c0    ))*TLEN + tt] = (v0 + db0) * s0 + m0;
            out[((size_t)(b*CINC + c0 + 1))*TLEN + tt] = (v1 + db1) * s1 + m1;
        }
    }
}

__global__ void k_final(float* out) {
    if (threadIdx.x == 0) { out[NRECON] = 0.f; out[NRECON+1] = g_l1 * 0.01f; }
}

// ---------------- launch ----------------
extern "C" void kernel_launch(void* const* d_in, const int* in_sizes, int n_in,
                              void* d_out, int out_size) {
    const float* x   = (const float*)d_in[0];
    const float* w1  = (const float*)d_in[1];
    const float* b1  = (const float*)d_in[2];
    const float* w2  = (const float*)d_in[3];
    const float* b2  = (const float*)d_in[4];
    const float* ssc = (const float*)d_in[5];
    const float* shp = (const float*)d_in[6];
    const float* dw  = (const float*)d_in[7];
    const float* db  = (const float*)d_in[8];
    float* out = (float*)d_out;

    const int SMEM4 = 2 * (8*80  + 8*32*17*2) * 4;   // 74752
    const int SMEM2 = 2 * (4*96  + 4*32*33*2) * 4;   // 70656
    const int SMEM1 = 2 * (2*127 + 2*32*65*2) * 4;   // 68592
    const int SMEMD = (128*66 + 6144) * 4;           // 58368
    cudaFuncSetAttribute(k_conv<4,17, 8,false>, cudaFuncAttributeMaxDynamicSharedMemorySize, SMEM4);
    cudaFuncSetAttribute(k_conv<2,33, 4,true >, cudaFuncAttributeMaxDynamicSharedMemorySize, SMEM2);
    cudaFuncSetAttribute(k_conv<1,64, 2,true >, cudaFuncAttributeMaxDynamicSharedMemorySize, SMEM1);
    cudaFuncSetAttribute(k_dec,                 cudaFuncAttributeMaxDynamicSharedMemorySize, SMEMD);

    k_stats<<<BB*CINC, 256>>>(x);
    k_shpnorm<<<(NAC*NAC + 255)/256, 256>>>(shp);
    k_buildW<4> <<<(NAC*NAC*4*17 + 255)/256, 256>>>(dw);
    k_buildW<2> <<<(NAC*NAC*2*33 + 255)/256, 256>>>(dw);
    k_buildW<32><<<(CINC*NAC*32*3 + 255)/256, 256>>>(dw);
    k_stem<<<dim3(LLAT/16, BB), 256>>>(x, w1, b1);
    k_point<<<dim3(LLAT/32, BB), 256>>>(w2, b2, ssc);
    k_pool4<<<BB*NAC, 128>>>();
    k_conv<4,17, 8,false><<<dim3(2, 2, BB*4), 256, SMEM4>>>();
    k_rp2<<<BB*NAC, 256>>>();
    k_conv<2,33, 4,true ><<<dim3(4, 2, BB*2), 256, SMEM2>>>();
    k_r1<<<BB*NAC, 512>>>();
    k_conv<1,64, 2,true ><<<dim3(8, 2, BB  ), 256, SMEM1>>>();
    k_dec<<<dim3(8, 6, BB), 256, SMEMD>>>(db, out);
    k_final<<<1, 32>>>(out);
}